// round 2
// baseline (speedup 1.0000x reference)
#include <cuda_runtime.h>
#include <math.h>

#define BATCH 1024
#define DD 128
#define G3 384
#define TT 96
#define NSTEP 95
#define S_ODE 132
#define S_GRU 388

// scratch (device globals -- no allocation allowed)
__device__ __align__(256) float g_traj[(size_t)TT * BATCH * DD];
__device__ __align__(256) float g_gi[(size_t)TT * BATCH * G3];
__device__ __align__(256) float g_h1[(size_t)TT * BATCH * DD];
__device__ __align__(256) float g_h2[(size_t)BATCH * DD];

__device__ __forceinline__ float sigm(float x) { return 1.0f / (1.0f + expf(-x)); }

// ---------------------------------------------------------------------------
// Phase 1: Dopri5 ODE integration. One warp handles 2 batch rows; lane l holds
// state elements 4l..4l+3. Matvec: out[j] = b[j] + sum_k y[k]*W[j][k], with
// W transposed in smem (Ws[k*S_ODE + j]).
// ---------------------------------------------------------------------------
__device__ __forceinline__ void ode_eval(const float (&a)[2][4], float (&o)[2][4],
                                         const float* __restrict__ Ws,
                                         const float (&bv)[4], int lane)
{
    float acc0[4], acc1[4];
#pragma unroll
    for (int m = 0; m < 4; m++) { acc0[m] = bv[m]; acc1[m] = bv[m]; }
#pragma unroll 8
    for (int kb = 0; kb < 32; kb++) {
#pragma unroll
        for (int mk = 0; mk < 4; mk++) {
            const int k = 4 * kb + mk;
            const float x0 = __shfl_sync(0xffffffffu, a[0][mk], kb);
            const float x1 = __shfl_sync(0xffffffffu, a[1][mk], kb);
            const float4 w = *(const float4*)(Ws + k * S_ODE + 4 * lane);
            acc0[0] = fmaf(x0, w.x, acc0[0]);
            acc0[1] = fmaf(x0, w.y, acc0[1]);
            acc0[2] = fmaf(x0, w.z, acc0[2]);
            acc0[3] = fmaf(x0, w.w, acc0[3]);
            acc1[0] = fmaf(x1, w.x, acc1[0]);
            acc1[1] = fmaf(x1, w.y, acc1[1]);
            acc1[2] = fmaf(x1, w.z, acc1[2]);
            acc1[3] = fmaf(x1, w.w, acc1[3]);
        }
    }
#pragma unroll
    for (int m = 0; m < 4; m++) { o[0][m] = tanhf(acc0[m]); o[1][m] = tanhf(acc1[m]); }
}

__global__ void __launch_bounds__(128)
ode_kernel(const float* __restrict__ yl, const float* __restrict__ yh,
           const float* __restrict__ W, const float* __restrict__ bias)
{
    extern __shared__ float sm[];
    const int tid = threadIdx.x;
    for (int idx = tid; idx < DD * DD; idx += 128) {
        const int j = idx >> 7, k = idx & 127;
        sm[k * S_ODE + j] = W[idx];
    }
    __syncthreads();

    const int lane = tid & 31, warp = tid >> 5;
    const int row0 = blockIdx.x * 8 + warp * 2;

    float bv[4];
#pragma unroll
    for (int m = 0; m < 4; m++) bv[m] = bias[4 * lane + m];

    float y[2][4];
#pragma unroll
    for (int r = 0; r < 2; r++) {
        const int row = row0 + r;
#pragma unroll
        for (int m = 0; m < 4; m++) {
            const int e = 4 * lane + m;
            y[r][m] = (e < 32) ? yl[row * 32 + e] : yh[row * 96 + (e - 32)];
        }
        *(float4*)(g_traj + (size_t)row * DD + 4 * lane) =
            make_float4(y[r][0], y[r][1], y[r][2], y[r][3]);
    }

    float k1[2][4], k2[2][4], k3[2][4], k4[2][4], k5[2][4], k6[2][4], ar[2][4];

    for (int st = 0; st < NSTEP; st++) {
        const float t0 = (float)st * (1.0f / 95.0f);
        const float t1 = (st == NSTEP - 1) ? 1.0f : (float)(st + 1) * (1.0f / 95.0f);
        const float dt = t1 - t0;

        ode_eval(y, k1, sm, bv, lane);

#pragma unroll
        for (int r = 0; r < 2; r++)
#pragma unroll
            for (int m = 0; m < 4; m++)
                ar[r][m] = y[r][m] + dt * (0.2f * k1[r][m]);
        ode_eval(ar, k2, sm, bv, lane);

#pragma unroll
        for (int r = 0; r < 2; r++)
#pragma unroll
            for (int m = 0; m < 4; m++) {
                float s = 0.075f * k1[r][m];
                s = fmaf(0.225f, k2[r][m], s);
                ar[r][m] = fmaf(dt, s, y[r][m]);
            }
        ode_eval(ar, k3, sm, bv, lane);

#pragma unroll
        for (int r = 0; r < 2; r++)
#pragma unroll
            for (int m = 0; m < 4; m++) {
                float s = 0.9777777777777777f * k1[r][m];
                s = fmaf(-3.7333333333333334f, k2[r][m], s);
                s = fmaf(3.5555555555555554f, k3[r][m], s);
                ar[r][m] = fmaf(dt, s, y[r][m]);
            }
        ode_eval(ar, k4, sm, bv, lane);

#pragma unroll
        for (int r = 0; r < 2; r++)
#pragma unroll
            for (int m = 0; m < 4; m++) {
                float s = 2.9525906892141633f * k1[r][m];
                s = fmaf(-11.595793324188385f, k2[r][m], s);
                s = fmaf(9.822892851699436f, k3[r][m], s);
                s = fmaf(-0.2908093278463649f, k4[r][m], s);
                ar[r][m] = fmaf(dt, s, y[r][m]);
            }
        ode_eval(ar, k5, sm, bv, lane);

#pragma unroll
        for (int r = 0; r < 2; r++)
#pragma unroll
            for (int m = 0; m < 4; m++) {
                float s = 2.8462752525252526f * k1[r][m];
                s = fmaf(-10.757575757575758f, k2[r][m], s);
                s = fmaf(8.906422717743473f, k3[r][m], s);
                s = fmaf(0.2784090909090909f, k4[r][m], s);
                s = fmaf(-0.2735313036020583f, k5[r][m], s);
                ar[r][m] = fmaf(dt, s, y[r][m]);
            }
        ode_eval(ar, k6, sm, bv, lane);

#pragma unroll
        for (int r = 0; r < 2; r++) {
#pragma unroll
            for (int m = 0; m < 4; m++) {
                float s = 0.09114583333333333f * k1[r][m];
                s = fmaf(0.44923629829290207f, k3[r][m], s);
                s = fmaf(0.6510416666666666f, k4[r][m], s);
                s = fmaf(-0.322376179245283f, k5[r][m], s);
                s = fmaf(0.13095238095238096f, k6[r][m], s);
                y[r][m] = fmaf(dt, s, y[r][m]);
            }
            *(float4*)(g_traj + ((size_t)(st + 1) * BATCH + row0 + r) * DD + 4 * lane) =
                make_float4(y[r][0], y[r][1], y[r][2], y[r][3]);
        }
    }
}

// ---------------------------------------------------------------------------
// Phase 2/4: gi = X @ W_ih^T + b_ih for all (t, row) items. Parallel GEMM.
// CTA handles 96 items (12 iters x 4 warps x 2 items), W transposed in smem.
// ---------------------------------------------------------------------------
__global__ void __launch_bounds__(128)
gi_kernel(const float* __restrict__ X, const float* __restrict__ Wih,
          const float* __restrict__ bih, float* __restrict__ gi)
{
    extern __shared__ float sm[];
    const int tid = threadIdx.x;
    for (int idx = tid; idx < G3 * DD; idx += 128) {
        const int j = idx >> 7, k = idx & 127;
        sm[k * S_GRU + j] = Wih[idx];
    }
    __syncthreads();

    const int lane = tid & 31, warp = tid >> 5;
    float bv[3][4];
#pragma unroll
    for (int g = 0; g < 3; g++)
#pragma unroll
        for (int m = 0; m < 4; m++) bv[g][m] = bih[128 * g + 4 * lane + m];

    for (int it = 0; it < 12; it++) {
        const int item = blockIdx.x * 96 + it * 8 + warp * 2;
        float a[2][4];
#pragma unroll
        for (int r = 0; r < 2; r++) {
            const float4 v = *(const float4*)(X + (size_t)(item + r) * DD + 4 * lane);
            a[r][0] = v.x; a[r][1] = v.y; a[r][2] = v.z; a[r][3] = v.w;
        }
        float acc[2][3][4];
#pragma unroll
        for (int r = 0; r < 2; r++)
#pragma unroll
            for (int g = 0; g < 3; g++)
#pragma unroll
                for (int m = 0; m < 4; m++) acc[r][g][m] = bv[g][m];

#pragma unroll 4
        for (int kb = 0; kb < 32; kb++) {
#pragma unroll
            for (int mk = 0; mk < 4; mk++) {
                const int k = 4 * kb + mk;
                const float x0 = __shfl_sync(0xffffffffu, a[0][mk], kb);
                const float x1 = __shfl_sync(0xffffffffu, a[1][mk], kb);
#pragma unroll
                for (int g = 0; g < 3; g++) {
                    const float4 w = *(const float4*)(sm + k * S_GRU + 128 * g + 4 * lane);
                    acc[0][g][0] = fmaf(x0, w.x, acc[0][g][0]);
                    acc[0][g][1] = fmaf(x0, w.y, acc[0][g][1]);
                    acc[0][g][2] = fmaf(x0, w.z, acc[0][g][2]);
                    acc[0][g][3] = fmaf(x0, w.w, acc[0][g][3]);
                    acc[1][g][0] = fmaf(x1, w.x, acc[1][g][0]);
                    acc[1][g][1] = fmaf(x1, w.y, acc[1][g][1]);
                    acc[1][g][2] = fmaf(x1, w.z, acc[1][g][2]);
                    acc[1][g][3] = fmaf(x1, w.w, acc[1][g][3]);
                }
            }
        }
#pragma unroll
        for (int r = 0; r < 2; r++)
#pragma unroll
            for (int g = 0; g < 3; g++)
                *(float4*)(gi + (size_t)(item + r) * G3 + 128 * g + 4 * lane) =
                    make_float4(acc[r][g][0], acc[r][g][1], acc[r][g][2], acc[r][g][3]);
    }
}

// ---------------------------------------------------------------------------
// Phase 3/5: GRU recurrent scan. Warp holds 2 rows' hidden state in registers.
// ---------------------------------------------------------------------------
__global__ void __launch_bounds__(128)
gru_kernel(const float* __restrict__ gi, const float* __restrict__ Whh,
           const float* __restrict__ bhh, float* __restrict__ otraj,
           float* __restrict__ olast)
{
    extern __shared__ float sm[];
    const int tid = threadIdx.x;
    for (int idx = tid; idx < G3 * DD; idx += 128) {
        const int j = idx >> 7, k = idx & 127;
        sm[k * S_GRU + j] = Whh[idx];
    }
    __syncthreads();

    const int lane = tid & 31, warp = tid >> 5;
    const int row0 = blockIdx.x * 8 + warp * 2;
    float bv[3][4];
#pragma unroll
    for (int g = 0; g < 3; g++)
#pragma unroll
        for (int m = 0; m < 4; m++) bv[g][m] = bhh[128 * g + 4 * lane + m];

    float h[2][4];
#pragma unroll
    for (int r = 0; r < 2; r++)
#pragma unroll
        for (int m = 0; m < 4; m++) h[r][m] = 0.0f;

    for (int t = 0; t < TT; t++) {
        float acc[2][3][4];
#pragma unroll
        for (int r = 0; r < 2; r++)
#pragma unroll
            for (int g = 0; g < 3; g++)
#pragma unroll
                for (int m = 0; m < 4; m++) acc[r][g][m] = bv[g][m];

#pragma unroll 4
        for (int kb = 0; kb < 32; kb++) {
#pragma unroll
            for (int mk = 0; mk < 4; mk++) {
                const int k = 4 * kb + mk;
                const float x0 = __shfl_sync(0xffffffffu, h[0][mk], kb);
                const float x1 = __shfl_sync(0xffffffffu, h[1][mk], kb);
#pragma unroll
                for (int g = 0; g < 3; g++) {
                    const float4 w = *(const float4*)(sm + k * S_GRU + 128 * g + 4 * lane);
                    acc[0][g][0] = fmaf(x0, w.x, acc[0][g][0]);
                    acc[0][g][1] = fmaf(x0, w.y, acc[0][g][1]);
                    acc[0][g][2] = fmaf(x0, w.z, acc[0][g][2]);
                    acc[0][g][3] = fmaf(x0, w.w, acc[0][g][3]);
                    acc[1][g][0] = fmaf(x1, w.x, acc[1][g][0]);
                    acc[1][g][1] = fmaf(x1, w.y, acc[1][g][1]);
                    acc[1][g][2] = fmaf(x1, w.z, acc[1][g][2]);
                    acc[1][g][3] = fmaf(x1, w.w, acc[1][g][3]);
                }
            }
        }

#pragma unroll
        for (int r = 0; r < 2; r++) {
            const float* gp = gi + ((size_t)t * BATCH + row0 + r) * G3 + 4 * lane;
            const float4 vr = *(const float4*)(gp);
            const float4 vz = *(const float4*)(gp + 128);
            const float4 vn = *(const float4*)(gp + 256);
            const float ir[4] = {vr.x, vr.y, vr.z, vr.w};
            const float iz[4] = {vz.x, vz.y, vz.z, vz.w};
            const float inn[4] = {vn.x, vn.y, vn.z, vn.w};
#pragma unroll
            for (int m = 0; m < 4; m++) {
                const float rg = sigm(ir[m] + acc[r][0][m]);
                const float zg = sigm(iz[m] + acc[r][1][m]);
                const float ng = tanhf(inn[m] + rg * acc[r][2][m]);
                h[r][m] = (1.0f - zg) * ng + zg * h[r][m];
            }
        }
        if (otraj) {
#pragma unroll
            for (int r = 0; r < 2; r++)
                *(float4*)(otraj + ((size_t)t * BATCH + row0 + r) * DD + 4 * lane) =
                    make_float4(h[r][0], h[r][1], h[r][2], h[r][3]);
        }
    }
    if (olast) {
#pragma unroll
        for (int r = 0; r < 2; r++)
            *(float4*)(olast + (size_t)(row0 + r) * DD + 4 * lane) =
                make_float4(h[r][0], h[r][1], h[r][2], h[r][3]);
    }
}

// ---------------------------------------------------------------------------
// Phase 6: FC head. hidden = gelu_exact(h2 @ W1^T + b1); pred = hidden @ W2^T + b2.
// Block: 8 rows, 256 threads. W tiles transposed in smem with padding.
// ---------------------------------------------------------------------------
__global__ void __launch_bounds__(256)
fc_kernel(const float* __restrict__ W1, const float* __restrict__ b1,
          const float* __restrict__ W2, const float* __restrict__ b2,
          float* __restrict__ out)
{
    extern __shared__ float sm[];
    float* hs = sm;          // 8*128
    float* hd = sm + 1024;   // 8*64
    float* wt = sm + 1536;   // max(128*68, 64*260) = 16640
    const int tid = threadIdx.x;
    const int row0 = blockIdx.x * 8;

    for (int idx = tid; idx < 8 * DD; idx += 256) hs[idx] = g_h2[(size_t)row0 * DD + idx];
    for (int idx = tid; idx < 64 * DD; idx += 256) {
        const int j = idx >> 7, k = idx & 127;
        wt[k * 68 + j] = W1[idx];
    }
    __syncthreads();

#pragma unroll
    for (int i = 0; i < 2; i++) {
        const int p = tid + 256 * i, r = p >> 6, j = p & 63;
        float acc = b1[j];
#pragma unroll 8
        for (int k = 0; k < DD; k++) acc = fmaf(hs[r * DD + k], wt[k * 68 + j], acc);
        hd[r * 64 + j] = acc * normcdff(acc);
    }

    for (int c = 0; c < 12; c++) {
        __syncthreads();
        for (int idx = tid; idx < 256 * 64; idx += 256) {
            const int jj = idx >> 6, k = idx & 63;
            wt[k * 260 + jj] = W2[(size_t)(c * 256 + jj) * 64 + k];
        }
        __syncthreads();
        const int j = c * 256 + tid;
        float acc[8];
#pragma unroll
        for (int r = 0; r < 8; r++) acc[r] = b2[j];
#pragma unroll 8
        for (int k = 0; k < 64; k++) {
            const float w = wt[k * 260 + tid];
#pragma unroll
            for (int r = 0; r < 8; r++) acc[r] = fmaf(hd[r * 64 + k], w, acc[r]);
        }
#pragma unroll
        for (int r = 0; r < 8; r++) out[(size_t)(row0 + r) * 3072 + j] = acc[r];
    }
}

// ---------------------------------------------------------------------------
extern "C" void kernel_launch(void* const* d_in, const int* in_sizes, int n_in,
                              void* d_out, int out_size)
{
    (void)in_sizes; (void)n_in; (void)out_size;
    // metadata order: x, yl, yh, W_ode, b_ode, W_ih0, W_hh0, b_ih0, b_hh0,
    //                 W_ih1, W_hh1, b_ih1, b_hh1, W1, b1, W2, b2
    const float* yl    = (const float*)d_in[1];
    const float* yh    = (const float*)d_in[2];
    const float* W_ode = (const float*)d_in[3];
    const float* b_ode = (const float*)d_in[4];
    const float* W_ih0 = (const float*)d_in[5];
    const float* W_hh0 = (const float*)d_in[6];
    const float* b_ih0 = (const float*)d_in[7];
    const float* b_hh0 = (const float*)d_in[8];
    const float* W_ih1 = (const float*)d_in[9];
    const float* W_hh1 = (const float*)d_in[10];
    const float* b_ih1 = (const float*)d_in[11];
    const float* b_hh1 = (const float*)d_in[12];
    const float* W1    = (const float*)d_in[13];
    const float* b1    = (const float*)d_in[14];
    const float* W2    = (const float*)d_in[15];
    const float* b2    = (const float*)d_in[16];
    float* out = (float*)d_out;

    float *traj, *gibuf, *h1, *h2;
    cudaGetSymbolAddress((void**)&traj,  g_traj);
    cudaGetSymbolAddress((void**)&gibuf, g_gi);
    cudaGetSymbolAddress((void**)&h1,    g_h1);
    cudaGetSymbolAddress((void**)&h2,    g_h2);

    const int SM_ODE = S_ODE * DD * 4;              // 67,584 B
    const int SM_GRU = S_GRU * DD * 4;              // 198,656 B
    const int SM_FC  = (1536 + 64 * 260) * 4;       // 72,704 B
    cudaFuncSetAttribute(ode_kernel, cudaFuncAttributeMaxDynamicSharedMemorySize, SM_ODE);
    cudaFuncSetAttribute(gi_kernel,  cudaFuncAttributeMaxDynamicSharedMemorySize, SM_GRU);
    cudaFuncSetAttribute(gru_kernel, cudaFuncAttributeMaxDynamicSharedMemorySize, SM_GRU);
    cudaFuncSetAttribute(fc_kernel,  cudaFuncAttributeMaxDynamicSharedMemorySize, SM_FC);

    ode_kernel<<<128, 128, SM_ODE>>>(yl, yh, W_ode, b_ode);
    gi_kernel <<<1024, 128, SM_GRU>>>(traj, W_ih0, b_ih0, gibuf);
    gru_kernel<<<128, 128, SM_GRU>>>(gibuf, W_hh0, b_hh0, h1, nullptr);
    gi_kernel <<<1024, 128, SM_GRU>>>(h1, W_ih1, b_ih1, gibuf);
    gru_kernel<<<128, 128, SM_GRU>>>(gibuf, W_hh1, b_hh1, nullptr, h2);
    fc_kernel <<<128, 256, SM_FC>>>(W1, b1, W2, b2, out);
}

// round 3
// speedup vs baseline: 1.4688x; 1.4688x over previous
#include <cuda_runtime.h>
#include <math.h>

#define BATCH 1024
#define DD 128
#define G3 384
#define TT 96
#define NSTEP 95
#define S_ODE 132
#define S_GRU 388

typedef unsigned long long u64;

__device__ __align__(256) float g_traj[(size_t)TT * BATCH * DD];
__device__ __align__(256) float g_gi[(size_t)TT * BATCH * G3];
__device__ __align__(256) float g_h1[(size_t)TT * BATCH * DD];
__device__ __align__(256) float g_h2[(size_t)BATCH * DD];

// ---- packed f32x2 + fast transcendental helpers ----
__device__ __forceinline__ u64 pack2(float lo, float hi) {
    u64 r; asm("mov.b64 %0,{%1,%2};" : "=l"(r) : "f"(lo), "f"(hi)); return r;
}
__device__ __forceinline__ u64 dup2(float v) { return pack2(v, v); }
__device__ __forceinline__ void unpk2(u64 v, float& lo, float& hi) {
    asm("mov.b64 {%0,%1},%2;" : "=f"(lo), "=f"(hi) : "l"(v));
}
__device__ __forceinline__ u64 ffma2(u64 a, u64 b, u64 c) {
    u64 d; asm("fma.rn.f32x2 %0,%1,%2,%3;" : "=l"(d) : "l"(a), "l"(b), "l"(c)); return d;
}
__device__ __forceinline__ u64 fadd2(u64 a, u64 b) {
    u64 d; asm("add.rn.f32x2 %0,%1,%2;" : "=l"(d) : "l"(a), "l"(b)); return d;
}
__device__ __forceinline__ float fex2(float x) { float r; asm("ex2.approx.f32 %0,%1;" : "=f"(r) : "f"(x)); return r; }
__device__ __forceinline__ float frcp(float x) { float r; asm("rcp.approx.f32 %0,%1;" : "=f"(r) : "f"(x)); return r; }
__device__ __forceinline__ float ftanh(float x) { return 1.0f - 2.0f * frcp(fex2(2.8853900817779268f * x) + 1.0f); }
__device__ __forceinline__ float fsigm(float x) { return frcp(1.0f + fex2(-1.4426950408889634f * x)); }

// ---------------------------------------------------------------------------
// Phase 1: Dopri5 ODE. 256 thr = 2 row-groups x k-split-4. Warp: 4 rows.
// ---------------------------------------------------------------------------
__device__ __forceinline__ void ode_eval(const float (&a)[4][4], float (&o)[4][4],
                                         const float* __restrict__ Ws, float* part,
                                         const u64 (&bv)[2], int lane, int gr, int ks,
                                         int buf)
{
    u64 acc[4][2];
#pragma unroll
    for (int r = 0; r < 4; r++) {
        acc[r][0] = (ks == 0) ? bv[0] : pack2(0.f, 0.f);
        acc[r][1] = (ks == 0) ? bv[1] : pack2(0.f, 0.f);
    }
#pragma unroll 4
    for (int kb = 8 * ks; kb < 8 * ks + 8; kb++) {
#pragma unroll
        for (int mk = 0; mk < 4; mk++) {
            const int k = 4 * kb + mk;
            const ulonglong2 w = *(const ulonglong2*)(Ws + k * S_ODE + 4 * lane);
#pragma unroll
            for (int r = 0; r < 4; r++) {
                const u64 xd = dup2(__shfl_sync(0xffffffffu, a[r][mk], kb));
                acc[r][0] = ffma2(xd, w.x, acc[r][0]);
                acc[r][1] = ffma2(xd, w.y, acc[r][1]);
            }
        }
    }
    float* base = part + (size_t)(((buf * 2 + gr) * 4 + ks) * 4) * 128 + 4 * lane;
#pragma unroll
    for (int r = 0; r < 4; r++)
        *(ulonglong2*)(base + r * 128) = make_ulonglong2(acc[r][0], acc[r][1]);
    __syncthreads();
    const float* gb = part + (size_t)((buf * 2 + gr) * 4) * 4 * 128 + 4 * lane;
#pragma unroll
    for (int r = 0; r < 4; r++) {
        u64 s0 = acc[r][0], s1 = acc[r][1];
#pragma unroll
        for (int q = 0; q < 4; q++) {
            if (q == ks) continue;
            const ulonglong2 p = *(const ulonglong2*)(gb + (q * 4 + r) * 128);
            s0 = fadd2(s0, p.x); s1 = fadd2(s1, p.y);
        }
        float f0, f1, f2, f3;
        unpk2(s0, f0, f1); unpk2(s1, f2, f3);
        o[r][0] = ftanh(f0); o[r][1] = ftanh(f1); o[r][2] = ftanh(f2); o[r][3] = ftanh(f3);
    }
}

__global__ void __launch_bounds__(256)
ode_kernel(const float* __restrict__ yl, const float* __restrict__ yh,
           const float* __restrict__ W, const float* __restrict__ bias)
{
    extern __shared__ float sm[];
    float* part = sm + S_ODE * DD;
    const int tid = threadIdx.x;
    for (int idx = tid; idx < DD * DD; idx += 256) {
        const int j = idx >> 7, k = idx & 127;
        sm[k * S_ODE + j] = W[idx];
    }
    __syncthreads();

    const int lane = tid & 31, warp = tid >> 5;
    const int gr = warp >> 2, ks = warp & 3;
    const int row0 = blockIdx.x * 8 + gr * 4;

    u64 bv[2];
    bv[0] = pack2(bias[4 * lane], bias[4 * lane + 1]);
    bv[1] = pack2(bias[4 * lane + 2], bias[4 * lane + 3]);

    float y[4][4];
#pragma unroll
    for (int r = 0; r < 4; r++) {
        const int row = row0 + r;
#pragma unroll
        for (int m = 0; m < 4; m++) {
            const int e = 4 * lane + m;
            y[r][m] = (e < 32) ? yl[row * 32 + e] : yh[row * 96 + (e - 32)];
        }
        if (ks == 0)
            *(float4*)(g_traj + (size_t)row * DD + 4 * lane) =
                make_float4(y[r][0], y[r][1], y[r][2], y[r][3]);
    }

    float k1[4][4], k2[4][4], k3[4][4], k4[4][4], k5[4][4], k6[4][4], ar[4][4];

    for (int st = 0; st < NSTEP; st++) {
        const float t0 = (float)st * (1.0f / 95.0f);
        const float t1 = (st == NSTEP - 1) ? 1.0f : (float)(st + 1) * (1.0f / 95.0f);
        const float dt = t1 - t0;

        ode_eval(y, k1, sm, part, bv, lane, gr, ks, 0);
#pragma unroll
        for (int r = 0; r < 4; r++)
#pragma unroll
            for (int m = 0; m < 4; m++)
                ar[r][m] = y[r][m] + dt * (0.2f * k1[r][m]);
        ode_eval(ar, k2, sm, part, bv, lane, gr, ks, 1);
#pragma unroll
        for (int r = 0; r < 4; r++)
#pragma unroll
            for (int m = 0; m < 4; m++) {
                float s = 0.075f * k1[r][m];
                s = fmaf(0.225f, k2[r][m], s);
                ar[r][m] = fmaf(dt, s, y[r][m]);
            }
        ode_eval(ar, k3, sm, part, bv, lane, gr, ks, 0);
#pragma unroll
        for (int r = 0; r < 4; r++)
#pragma unroll
            for (int m = 0; m < 4; m++) {
                float s = 0.9777777777777777f * k1[r][m];
                s = fmaf(-3.7333333333333334f, k2[r][m], s);
                s = fmaf(3.5555555555555554f, k3[r][m], s);
                ar[r][m] = fmaf(dt, s, y[r][m]);
            }
        ode_eval(ar, k4, sm, part, bv, lane, gr, ks, 1);
#pragma unroll
        for (int r = 0; r < 4; r++)
#pragma unroll
            for (int m = 0; m < 4; m++) {
                float s = 2.9525906892141633f * k1[r][m];
                s = fmaf(-11.595793324188385f, k2[r][m], s);
                s = fmaf(9.822892851699436f, k3[r][m], s);
                s = fmaf(-0.2908093278463649f, k4[r][m], s);
                ar[r][m] = fmaf(dt, s, y[r][m]);
            }
        ode_eval(ar, k5, sm, part, bv, lane, gr, ks, 0);
#pragma unroll
        for (int r = 0; r < 4; r++)
#pragma unroll
            for (int m = 0; m < 4; m++) {
                float s = 2.8462752525252526f * k1[r][m];
                s = fmaf(-10.757575757575758f, k2[r][m], s);
                s = fmaf(8.906422717743473f, k3[r][m], s);
                s = fmaf(0.2784090909090909f, k4[r][m], s);
                s = fmaf(-0.2735313036020583f, k5[r][m], s);
                ar[r][m] = fmaf(dt, s, y[r][m]);
            }
        ode_eval(ar, k6, sm, part, bv, lane, gr, ks, 1);

#pragma unroll
        for (int r = 0; r < 4; r++) {
#pragma unroll
            for (int m = 0; m < 4; m++) {
                float s = 0.09114583333333333f * k1[r][m];
                s = fmaf(0.44923629829290207f, k3[r][m], s);
                s = fmaf(0.6510416666666666f, k4[r][m], s);
                s = fmaf(-0.322376179245283f, k5[r][m], s);
                s = fmaf(0.13095238095238096f, k6[r][m], s);
                y[r][m] = fmaf(dt, s, y[r][m]);
            }
            if (ks == 0)
                *(float4*)(g_traj + ((size_t)(st + 1) * BATCH + row0 + r) * DD + 4 * lane) =
                    make_float4(y[r][0], y[r][1], y[r][2], y[r][3]);
        }
    }
}

// ---------------------------------------------------------------------------
// Phase 2/4: gi = X @ W_ih^T + b_ih. 256 thr = 8 warps x 8 items, 12 iters.
// ---------------------------------------------------------------------------
__global__ void __launch_bounds__(256)
gi_kernel(const float* __restrict__ X, const float* __restrict__ Wih,
          const float* __restrict__ bih, float* __restrict__ gi)
{
    extern __shared__ float sm[];
    const int tid = threadIdx.x;
    for (int idx = tid; idx < G3 * DD; idx += 256) {
        const int j = idx >> 7, k = idx & 127;
        sm[k * S_GRU + j] = Wih[idx];
    }
    __syncthreads();

    const int lane = tid & 31, warp = tid >> 5;
    u64 bv[3][2];
#pragma unroll
    for (int g = 0; g < 3; g++) {
        bv[g][0] = pack2(bih[128 * g + 4 * lane], bih[128 * g + 4 * lane + 1]);
        bv[g][1] = pack2(bih[128 * g + 4 * lane + 2], bih[128 * g + 4 * lane + 3]);
    }
    const float* wb = sm + 4 * lane;

#pragma unroll 1
    for (int it = 0; it < 12; it++) {
        const int item = blockIdx.x * 768 + it * 64 + warp * 8;
        float a[8][4];
#pragma unroll
        for (int i = 0; i < 8; i++) {
            const float4 v = *(const float4*)(X + (size_t)(item + i) * DD + 4 * lane);
            a[i][0] = v.x; a[i][1] = v.y; a[i][2] = v.z; a[i][3] = v.w;
        }
        u64 acc[8][3][2];
#pragma unroll
        for (int i = 0; i < 8; i++)
#pragma unroll
            for (int g = 0; g < 3; g++) { acc[i][g][0] = bv[g][0]; acc[i][g][1] = bv[g][1]; }

#pragma unroll 1
        for (int kb = 0; kb < 32; kb++) {
#pragma unroll
            for (int mk = 0; mk < 4; mk++) {
                const int k = 4 * kb + mk;
                const ulonglong2 w0 = *(const ulonglong2*)(wb + k * S_GRU);
                const ulonglong2 w1 = *(const ulonglong2*)(wb + k * S_GRU + 128);
                const ulonglong2 w2 = *(const ulonglong2*)(wb + k * S_GRU + 256);
#pragma unroll
                for (int i = 0; i < 8; i++) {
                    const u64 xd = dup2(__shfl_sync(0xffffffffu, a[i][mk], kb));
                    acc[i][0][0] = ffma2(xd, w0.x, acc[i][0][0]);
                    acc[i][0][1] = ffma2(xd, w0.y, acc[i][0][1]);
                    acc[i][1][0] = ffma2(xd, w1.x, acc[i][1][0]);
                    acc[i][1][1] = ffma2(xd, w1.y, acc[i][1][1]);
                    acc[i][2][0] = ffma2(xd, w2.x, acc[i][2][0]);
                    acc[i][2][1] = ffma2(xd, w2.y, acc[i][2][1]);
                }
            }
        }
#pragma unroll
        for (int i = 0; i < 8; i++)
#pragma unroll
            for (int g = 0; g < 3; g++)
                *(ulonglong2*)(gi + (size_t)(item + i) * G3 + 128 * g + 4 * lane) =
                    make_ulonglong2(acc[i][g][0], acc[i][g][1]);
    }
}

// ---------------------------------------------------------------------------
// Phase 3/5: GRU scan. 384 thr = 2 row-groups x 3 gates x k-split-2.
// ---------------------------------------------------------------------------
__global__ void __launch_bounds__(384)
gru_kernel(const float* __restrict__ gi, const float* __restrict__ Whh,
           const float* __restrict__ bhh, float* __restrict__ otraj,
           float* __restrict__ olast)
{
    extern __shared__ float sm[];
    float* pp = sm + DD * S_GRU;   // [gr][g][r][128] ks==1 partials
    float* gb = pp + 3072;         // [gr][g][r][128] gate values
    const int tid = threadIdx.x;
    for (int idx = tid; idx < G3 * DD; idx += 384) {
        const int j = idx >> 7, k = idx & 127;
        sm[k * S_GRU + j] = Whh[idx];
    }
    __syncthreads();

    const int lane = tid & 31, wid = tid >> 5;
    const int gr = wid / 6, rem = wid - gr * 6;
    const int g = rem >> 1, ks = rem & 1;
    const int row0 = blockIdx.x * 8 + gr * 4;

    u64 bv0 = pack2(0.f, 0.f), bv1 = bv0;
    if (ks == 0) {
        bv0 = pack2(bhh[g * 128 + 4 * lane], bhh[g * 128 + 4 * lane + 1]);
        bv1 = pack2(bhh[g * 128 + 4 * lane + 2], bhh[g * 128 + 4 * lane + 3]);
    }
    const float* wb = sm + g * 128 + 4 * lane;
    float* ppme = pp + (size_t)((gr * 3 + g) * 4) * 128 + 4 * lane;
    float* gbg  = gb + (size_t)(gr * 12) * 128 + 4 * lane;
    float h[4][4];
#pragma unroll
    for (int r = 0; r < 4; r++)
#pragma unroll
        for (int m = 0; m < 4; m++) h[r][m] = 0.0f;

    for (int t = 0; t < TT; t++) {
        float4 gvec[4];
        if (ks == 0) {
#pragma unroll
            for (int r = 0; r < 4; r++)
                gvec[r] = *(const float4*)(gi + ((size_t)t * BATCH + row0 + r) * G3 +
                                           g * 128 + 4 * lane);
        }
        u64 acc[4][2];
#pragma unroll
        for (int r = 0; r < 4; r++) { acc[r][0] = bv0; acc[r][1] = bv1; }

#pragma unroll 4
        for (int kb = 16 * ks; kb < 16 * ks + 16; kb++) {
#pragma unroll
            for (int mk = 0; mk < 4; mk++) {
                const int k = 4 * kb + mk;
                const ulonglong2 w = *(const ulonglong2*)(wb + k * S_GRU);
#pragma unroll
                for (int r = 0; r < 4; r++) {
                    const u64 xd = dup2(__shfl_sync(0xffffffffu, h[r][mk], kb));
                    acc[r][0] = ffma2(xd, w.x, acc[r][0]);
                    acc[r][1] = ffma2(xd, w.y, acc[r][1]);
                }
            }
        }
        if (ks == 1) {
#pragma unroll
            for (int r = 0; r < 4; r++)
                *(ulonglong2*)(ppme + r * 128) = make_ulonglong2(acc[r][0], acc[r][1]);
        }
        __syncthreads();   // A

        float vals[4][4];
        if (ks == 0) {
#pragma unroll
            for (int r = 0; r < 4; r++) {
                const ulonglong2 p = *(const ulonglong2*)(ppme + r * 128);
                const u64 s0 = fadd2(acc[r][0], p.x), s1 = fadd2(acc[r][1], p.y);
                float a0, a1, a2, a3;
                unpk2(s0, a0, a1); unpk2(s1, a2, a3);
                if (g < 2) {
                    vals[r][0] = fsigm(gvec[r].x + a0);
                    vals[r][1] = fsigm(gvec[r].y + a1);
                    vals[r][2] = fsigm(gvec[r].z + a2);
                    vals[r][3] = fsigm(gvec[r].w + a3);
                } else {
                    vals[r][0] = a0; vals[r][1] = a1; vals[r][2] = a2; vals[r][3] = a3;
                }
            }
            if (g < 2) {
#pragma unroll
                for (int r = 0; r < 4; r++)
                    *(float4*)(gbg + (g * 4 + r) * 128) =
                        make_float4(vals[r][0], vals[r][1], vals[r][2], vals[r][3]);
            }
        }
        __syncthreads();   // B

        if (ks == 0 && g == 2) {
#pragma unroll
            for (int r = 0; r < 4; r++) {
                const float4 rv = *(const float4*)(gbg + r * 128);
                vals[r][0] = ftanh(gvec[r].x + rv.x * vals[r][0]);
                vals[r][1] = ftanh(gvec[r].y + rv.y * vals[r][1]);
                vals[r][2] = ftanh(gvec[r].z + rv.z * vals[r][2]);
                vals[r][3] = ftanh(gvec[r].w + rv.w * vals[r][3]);
                *(float4*)(gbg + (8 + r) * 128) =
                    make_float4(vals[r][0], vals[r][1], vals[r][2], vals[r][3]);
            }
        }
        __syncthreads();   // C

#pragma unroll
        for (int r = 0; r < 4; r++) {
            const float4 zv = *(const float4*)(gbg + (4 + r) * 128);
            const float4 nv = *(const float4*)(gbg + (8 + r) * 128);
            h[r][0] = nv.x + zv.x * (h[r][0] - nv.x);
            h[r][1] = nv.y + zv.y * (h[r][1] - nv.y);
            h[r][2] = nv.z + zv.z * (h[r][2] - nv.z);
            h[r][3] = nv.w + zv.w * (h[r][3] - nv.w);
        }
        if (otraj && g == 0 && ks == 0) {
#pragma unroll
            for (int r = 0; r < 4; r++)
                *(float4*)(otraj + ((size_t)t * BATCH + row0 + r) * DD + 4 * lane) =
                    make_float4(h[r][0], h[r][1], h[r][2], h[r][3]);
        }
    }
    if (olast && g == 0 && ks == 0) {
#pragma unroll
        for (int r = 0; r < 4; r++)
            *(float4*)(olast + (size_t)(row0 + r) * DD + 4 * lane) =
                make_float4(h[r][0], h[r][1], h[r][2], h[r][3]);
    }
}

// ---------------------------------------------------------------------------
// Phase 6: FC head (unchanged from R1).
// ---------------------------------------------------------------------------
__global__ void __launch_bounds__(256)
fc_kernel(const float* __restrict__ W1, const float* __restrict__ b1,
          const float* __restrict__ W2, const float* __restrict__ b2,
          float* __restrict__ out)
{
    extern __shared__ float sm[];
    float* hs = sm;
    float* hd = sm + 1024;
    float* wt = sm + 1536;
    const int tid = threadIdx.x;
    const int row0 = blockIdx.x * 8;

    for (int idx = tid; idx < 8 * DD; idx += 256) hs[idx] = g_h2[(size_t)row0 * DD + idx];
    for (int idx = tid; idx < 64 * DD; idx += 256) {
        const int j = idx >> 7, k = idx & 127;
        wt[k * 68 + j] = W1[idx];
    }
    __syncthreads();

#pragma unroll
    for (int i = 0; i < 2; i++) {
        const int p = tid + 256 * i, r = p >> 6, j = p & 63;
        float acc = b1[j];
#pragma unroll 8
        for (int k = 0; k < DD; k++) acc = fmaf(hs[r * DD + k], wt[k * 68 + j], acc);
        hd[r * 64 + j] = acc * normcdff(acc);
    }

    for (int c = 0; c < 12; c++) {
        __syncthreads();
        for (int idx = tid; idx < 256 * 64; idx += 256) {
            const int jj = idx >> 6, k = idx & 63;
            wt[k * 260 + jj] = W2[(size_t)(c * 256 + jj) * 64 + k];
        }
        __syncthreads();
        const int j = c * 256 + tid;
        float acc[8];
#pragma unroll
        for (int r = 0; r < 8; r++) acc[r] = b2[j];
#pragma unroll 8
        for (int k = 0; k < 64; k++) {
            const float w = wt[k * 260 + tid];
#pragma unroll
            for (int r = 0; r < 8; r++) acc[r] = fmaf(hd[r * 64 + k], w, acc[r]);
        }
#pragma unroll
        for (int r = 0; r < 8; r++) out[(size_t)(row0 + r) * 3072 + j] = acc[r];
    }
}

// ---------------------------------------------------------------------------
extern "C" void kernel_launch(void* const* d_in, const int* in_sizes, int n_in,
                              void* d_out, int out_size)
{
    (void)in_sizes; (void)n_in; (void)out_size;
    const float* yl    = (const float*)d_in[1];
    const float* yh    = (const float*)d_in[2];
    const float* W_ode = (const float*)d_in[3];
    const float* b_ode = (const float*)d_in[4];
    const float* W_ih0 = (const float*)d_in[5];
    const float* W_hh0 = (const float*)d_in[6];
    const float* b_ih0 = (const float*)d_in[7];
    const float* b_hh0 = (const float*)d_in[8];
    const float* W_ih1 = (const float*)d_in[9];
    const float* W_hh1 = (const float*)d_in[10];
    const float* b_ih1 = (const float*)d_in[11];
    const float* b_hh1 = (const float*)d_in[12];
    const float* W1    = (const float*)d_in[13];
    const float* b1    = (const float*)d_in[14];
    const float* W2    = (const float*)d_in[15];
    const float* b2    = (const float*)d_in[16];
    float* out = (float*)d_out;

    float *traj, *gibuf, *h1, *h2;
    cudaGetSymbolAddress((void**)&traj,  g_traj);
    cudaGetSymbolAddress((void**)&gibuf, g_gi);
    cudaGetSymbolAddress((void**)&h1,    g_h1);
    cudaGetSymbolAddress((void**)&h2,    g_h2);

    const int SM_ODE = (S_ODE * DD + 16384) * 4;          // 133,120 B
    const int SM_GI  = S_GRU * DD * 4;                    // 198,656 B
    const int SM_GRU2 = (S_GRU * DD + 6144) * 4;          // 223,232 B
    const int SM_FC  = (1536 + 64 * 260) * 4;             // 72,704 B
    cudaFuncSetAttribute(ode_kernel, cudaFuncAttributeMaxDynamicSharedMemorySize, SM_ODE);
    cudaFuncSetAttribute(gi_kernel,  cudaFuncAttributeMaxDynamicSharedMemorySize, SM_GI);
    cudaFuncSetAttribute(gru_kernel, cudaFuncAttributeMaxDynamicSharedMemorySize, SM_GRU2);
    cudaFuncSetAttribute(fc_kernel,  cudaFuncAttributeMaxDynamicSharedMemorySize, SM_FC);

    ode_kernel<<<128, 256, SM_ODE>>>(yl, yh, W_ode, b_ode);
    gi_kernel <<<128, 256, SM_GI>>>(traj, W_ih0, b_ih0, gibuf);
    gru_kernel<<<128, 384, SM_GRU2>>>(gibuf, W_hh0, b_hh0, h1, nullptr);
    gi_kernel <<<128, 256, SM_GI>>>(h1, W_ih1, b_ih1, gibuf);
    gru_kernel<<<128, 384, SM_GRU2>>>(gibuf, W_hh1, b_hh1, nullptr, h2);
    fc_kernel <<<128, 256, SM_FC>>>(W1, b1, W2, b2, out);
}

// round 4
// speedup vs baseline: 1.7006x; 1.1578x over previous
#include <cuda_runtime.h>
#include <math.h>

#define BATCH 1024
#define DD 128
#define G3 384
#define TT 96
#define NSTEP 95
#define S_ODE 132
#define S_GRU 388

typedef unsigned long long u64;

__device__ __align__(256) float g_traj[(size_t)TT * BATCH * DD];
__device__ __align__(256) float g_gi[(size_t)TT * BATCH * G3];
__device__ __align__(256) float g_h1[(size_t)TT * BATCH * DD];
__device__ __align__(256) float g_h2[(size_t)BATCH * DD];

// ---- packed f32x2 + fast transcendental helpers ----
__device__ __forceinline__ u64 pack2(float lo, float hi) {
    u64 r; asm("mov.b64 %0,{%1,%2};" : "=l"(r) : "f"(lo), "f"(hi)); return r;
}
__device__ __forceinline__ u64 dup2(float v) { return pack2(v, v); }
__device__ __forceinline__ void unpk2(u64 v, float& lo, float& hi) {
    asm("mov.b64 {%0,%1},%2;" : "=f"(lo), "=f"(hi) : "l"(v));
}
__device__ __forceinline__ u64 ffma2(u64 a, u64 b, u64 c) {
    u64 d; asm("fma.rn.f32x2 %0,%1,%2,%3;" : "=l"(d) : "l"(a), "l"(b), "l"(c)); return d;
}
__device__ __forceinline__ u64 fadd2(u64 a, u64 b) {
    u64 d; asm("add.rn.f32x2 %0,%1,%2;" : "=l"(d) : "l"(a), "l"(b)); return d;
}
__device__ __forceinline__ float fex2(float x) { float r; asm("ex2.approx.f32 %0,%1;" : "=f"(r) : "f"(x)); return r; }
__device__ __forceinline__ float frcp(float x) { float r; asm("rcp.approx.f32 %0,%1;" : "=f"(r) : "f"(x)); return r; }
__device__ __forceinline__ float ftanh(float x) { return 1.0f - 2.0f * frcp(fex2(2.8853900817779268f * x) + 1.0f); }
__device__ __forceinline__ float fsigm(float x) { return frcp(1.0f + fex2(-1.4426950408889634f * x)); }

// ---------------------------------------------------------------------------
// Phase 1: Dopri5 ODE. 256 thr = 8 warps = 2 row-groups x 4 k-slices.
// Warp (gr,q) computes k-slice q of the matvec for all 4 rows of its group,
// then owns row q's reduction, tanh, RK combo, and dup'd-activation store.
// xs layout: [gr][row][k] as duplicated float2 pairs (u64).
// ---------------------------------------------------------------------------
__device__ __forceinline__ void ode_mv(const float* __restrict__ Ws, const u64* xsu,
                                       float* part, const float (&bv)[4],
                                       int lane, int gr, int q, float (&ko)[4])
{
    u64 acc[4][2];
#pragma unroll
    for (int r = 0; r < 4; r++) { acc[r][0] = pack2(0.f, 0.f); acc[r][1] = pack2(0.f, 0.f); }
    const int kbase = 32 * q;
#pragma unroll 4
    for (int kk = 0; kk < 32; kk += 2) {
        const int k = kbase + kk;
        const ulonglong2 x0 = *(const ulonglong2*)(xsu + (gr * 4 + 0) * 128 + k);
        const ulonglong2 x1 = *(const ulonglong2*)(xsu + (gr * 4 + 1) * 128 + k);
        const ulonglong2 x2 = *(const ulonglong2*)(xsu + (gr * 4 + 2) * 128 + k);
        const ulonglong2 x3 = *(const ulonglong2*)(xsu + (gr * 4 + 3) * 128 + k);
        const ulonglong2 wA = *(const ulonglong2*)(Ws + k * S_ODE + 4 * lane);
        const ulonglong2 wB = *(const ulonglong2*)(Ws + (k + 1) * S_ODE + 4 * lane);
        acc[0][0] = ffma2(x0.x, wA.x, acc[0][0]); acc[0][1] = ffma2(x0.x, wA.y, acc[0][1]);
        acc[1][0] = ffma2(x1.x, wA.x, acc[1][0]); acc[1][1] = ffma2(x1.x, wA.y, acc[1][1]);
        acc[2][0] = ffma2(x2.x, wA.x, acc[2][0]); acc[2][1] = ffma2(x2.x, wA.y, acc[2][1]);
        acc[3][0] = ffma2(x3.x, wA.x, acc[3][0]); acc[3][1] = ffma2(x3.x, wA.y, acc[3][1]);
        acc[0][0] = ffma2(x0.y, wB.x, acc[0][0]); acc[0][1] = ffma2(x0.y, wB.y, acc[0][1]);
        acc[1][0] = ffma2(x1.y, wB.x, acc[1][0]); acc[1][1] = ffma2(x1.y, wB.y, acc[1][1]);
        acc[2][0] = ffma2(x2.y, wB.x, acc[2][0]); acc[2][1] = ffma2(x2.y, wB.y, acc[2][1]);
        acc[3][0] = ffma2(x3.y, wB.x, acc[3][0]); acc[3][1] = ffma2(x3.y, wB.y, acc[3][1]);
    }
    float* pme = part + (size_t)((gr * 4 + q) * 4) * 128 + 4 * lane;
#pragma unroll
    for (int r = 0; r < 4; r++)
        *(ulonglong2*)(pme + r * 128) = make_ulonglong2(acc[r][0], acc[r][1]);
    __syncthreads();   // S1
    u64 s0 = acc[q][0], s1 = acc[q][1];
#pragma unroll
    for (int p = 0; p < 4; p++) {
        if (p == q) continue;
        const ulonglong2 v = *(const ulonglong2*)(part + (size_t)((gr * 4 + p) * 4 + q) * 128 + 4 * lane);
        s0 = fadd2(s0, v.x); s1 = fadd2(s1, v.y);
    }
    float f0, f1, f2, f3;
    unpk2(s0, f0, f1); unpk2(s1, f2, f3);
    ko[0] = ftanh(f0 + bv[0]); ko[1] = ftanh(f1 + bv[1]);
    ko[2] = ftanh(f2 + bv[2]); ko[3] = ftanh(f3 + bv[3]);
}

__global__ void __launch_bounds__(256)
ode_kernel(const float* __restrict__ yl, const float* __restrict__ yh,
           const float* __restrict__ W, const float* __restrict__ bias)
{
    extern __shared__ float sm[];
    float* part = sm + S_ODE * DD;   // 4096 floats
    float* xsf  = part + 4096;       // 2048 floats
    u64* xsu = (u64*)xsf;
    const int tid = threadIdx.x;
    for (int idx = tid; idx < DD * DD; idx += 256) {
        const int j = idx >> 7, k = idx & 127;
        sm[k * S_ODE + j] = W[idx];
    }
    const int lane = tid & 31, warp = tid >> 5;
    const int gr = warp >> 2, q = warp & 3;
    const int row = blockIdx.x * 8 + gr * 4 + q;

    float bv[4];
#pragma unroll
    for (int m = 0; m < 4; m++) bv[m] = bias[4 * lane + m];

    float y[4];
#pragma unroll
    for (int m = 0; m < 4; m++) {
        const int e = 4 * lane + m;
        y[m] = (e < 32) ? yl[row * 32 + e] : yh[row * 96 + (e - 32)];
    }
    *(float4*)(g_traj + (size_t)row * DD + 4 * lane) = make_float4(y[0], y[1], y[2], y[3]);
    float* xme = xsf + (size_t)((gr * 4 + q) * 128 + 4 * lane) * 2;
    *(float4*)(xme)     = make_float4(y[0], y[0], y[1], y[1]);
    *(float4*)(xme + 4) = make_float4(y[2], y[2], y[3], y[3]);
    __syncthreads();

    float k1[4], k2[4], k3[4], k4[4], k5[4], k6[4], ar[4];
    const float dt = 1.0f / 95.0f;

#define ODE_STORE_AR() do { \
    *(float4*)(xme)     = make_float4(ar[0], ar[0], ar[1], ar[1]); \
    *(float4*)(xme + 4) = make_float4(ar[2], ar[2], ar[3], ar[3]); \
    __syncthreads(); } while (0)

    for (int st = 0; st < NSTEP; st++) {
        ode_mv(sm, xsu, part, bv, lane, gr, q, k1);
#pragma unroll
        for (int m = 0; m < 4; m++) ar[m] = fmaf(dt * 0.2f, k1[m], y[m]);
        ODE_STORE_AR();

        ode_mv(sm, xsu, part, bv, lane, gr, q, k2);
#pragma unroll
        for (int m = 0; m < 4; m++) {
            float s = 0.075f * k1[m];
            s = fmaf(0.225f, k2[m], s);
            ar[m] = fmaf(dt, s, y[m]);
        }
        ODE_STORE_AR();

        ode_mv(sm, xsu, part, bv, lane, gr, q, k3);
#pragma unroll
        for (int m = 0; m < 4; m++) {
            float s = 0.9777777777777777f * k1[m];
            s = fmaf(-3.7333333333333334f, k2[m], s);
            s = fmaf(3.5555555555555554f, k3[m], s);
            ar[m] = fmaf(dt, s, y[m]);
        }
        ODE_STORE_AR();

        ode_mv(sm, xsu, part, bv, lane, gr, q, k4);
#pragma unroll
        for (int m = 0; m < 4; m++) {
            float s = 2.9525906892141633f * k1[m];
            s = fmaf(-11.595793324188385f, k2[m], s);
            s = fmaf(9.822892851699436f, k3[m], s);
            s = fmaf(-0.2908093278463649f, k4[m], s);
            ar[m] = fmaf(dt, s, y[m]);
        }
        ODE_STORE_AR();

        ode_mv(sm, xsu, part, bv, lane, gr, q, k5);
#pragma unroll
        for (int m = 0; m < 4; m++) {
            float s = 2.8462752525252526f * k1[m];
            s = fmaf(-10.757575757575758f, k2[m], s);
            s = fmaf(8.906422717743473f, k3[m], s);
            s = fmaf(0.2784090909090909f, k4[m], s);
            s = fmaf(-0.2735313036020583f, k5[m], s);
            ar[m] = fmaf(dt, s, y[m]);
        }
        ODE_STORE_AR();

        ode_mv(sm, xsu, part, bv, lane, gr, q, k6);
#pragma unroll
        for (int m = 0; m < 4; m++) {
            float s = 0.09114583333333333f * k1[m];
            s = fmaf(0.44923629829290207f, k3[m], s);
            s = fmaf(0.6510416666666666f, k4[m], s);
            s = fmaf(-0.322376179245283f, k5[m], s);
            s = fmaf(0.13095238095238096f, k6[m], s);
            y[m] = fmaf(dt, s, y[m]);
        }
        *(float4*)(xme)     = make_float4(y[0], y[0], y[1], y[1]);
        *(float4*)(xme + 4) = make_float4(y[2], y[2], y[3], y[3]);
        *(float4*)(g_traj + ((size_t)(st + 1) * BATCH + row) * DD + 4 * lane) =
            make_float4(y[0], y[1], y[2], y[3]);
        __syncthreads();
    }
#undef ODE_STORE_AR
}

// ---------------------------------------------------------------------------
// Phase 2/4: gi = X @ W_ih^T + b_ih. 512 thr = 16 warps x 4 items, 12 iters.
// ---------------------------------------------------------------------------
__global__ void __launch_bounds__(512)
gi_kernel(const float* __restrict__ X, const float* __restrict__ Wih,
          const float* __restrict__ bih, float* __restrict__ gi)
{
    extern __shared__ float sm[];
    const int tid = threadIdx.x;
    for (int idx = tid; idx < G3 * DD; idx += 512) {
        const int j = idx >> 7, k = idx & 127;
        sm[k * S_GRU + j] = Wih[idx];
    }
    __syncthreads();

    const int lane = tid & 31, warp = tid >> 5;
    u64 bv[3][2];
#pragma unroll
    for (int g = 0; g < 3; g++) {
        bv[g][0] = pack2(bih[128 * g + 4 * lane], bih[128 * g + 4 * lane + 1]);
        bv[g][1] = pack2(bih[128 * g + 4 * lane + 2], bih[128 * g + 4 * lane + 3]);
    }
    const float* wb = sm + 4 * lane;

#pragma unroll 1
    for (int it = 0; it < 12; it++) {
        const int item = blockIdx.x * 768 + it * 64 + warp * 4;
        float a[4][4];
#pragma unroll
        for (int i = 0; i < 4; i++) {
            const float4 v = *(const float4*)(X + (size_t)(item + i) * DD + 4 * lane);
            a[i][0] = v.x; a[i][1] = v.y; a[i][2] = v.z; a[i][3] = v.w;
        }
        u64 acc[4][3][2];
#pragma unroll
        for (int i = 0; i < 4; i++)
#pragma unroll
            for (int g = 0; g < 3; g++) { acc[i][g][0] = bv[g][0]; acc[i][g][1] = bv[g][1]; }

#pragma unroll 2
        for (int kb = 0; kb < 32; kb++) {
#pragma unroll
            for (int mk = 0; mk < 4; mk++) {
                const int k = 4 * kb + mk;
                const ulonglong2 w0 = *(const ulonglong2*)(wb + k * S_GRU);
                const ulonglong2 w1 = *(const ulonglong2*)(wb + k * S_GRU + 128);
                const ulonglong2 w2 = *(const ulonglong2*)(wb + k * S_GRU + 256);
#pragma unroll
                for (int i = 0; i < 4; i++) {
                    const u64 xd = dup2(__shfl_sync(0xffffffffu, a[i][mk], kb));
                    acc[i][0][0] = ffma2(xd, w0.x, acc[i][0][0]);
                    acc[i][0][1] = ffma2(xd, w0.y, acc[i][0][1]);
                    acc[i][1][0] = ffma2(xd, w1.x, acc[i][1][0]);
                    acc[i][1][1] = ffma2(xd, w1.y, acc[i][1][1]);
                    acc[i][2][0] = ffma2(xd, w2.x, acc[i][2][0]);
                    acc[i][2][1] = ffma2(xd, w2.y, acc[i][2][1]);
                }
            }
        }
#pragma unroll
        for (int i = 0; i < 4; i++)
#pragma unroll
            for (int g = 0; g < 3; g++)
                *(ulonglong2*)(gi + (size_t)(item + i) * G3 + 128 * g + 4 * lane) =
                    make_ulonglong2(acc[i][g][0], acc[i][g][1]);
    }
}

// ---------------------------------------------------------------------------
// Phase 3/5: GRU scan. 384 thr = 2 row-groups x 3 gates x k-split-2.
// h lives dup'd in smem xs; (g==2,ks==0) warp owns finalization + h regs.
// pbuf doubles as raw-partial buffer (ks1) and gate-value buffer (ks0).
// ---------------------------------------------------------------------------
__global__ void __launch_bounds__(384)
gru_kernel(const float* __restrict__ gi, const float* __restrict__ Whh,
           const float* __restrict__ bhh, float* __restrict__ otraj,
           float* __restrict__ olast)
{
    extern __shared__ float sm[];
    float* pbuf = sm + DD * S_GRU;   // 3072 floats: [(gr*3+g)*4 + r][128]
    float* xsf  = pbuf + 3072;       // 2048 floats: [gr][row][k] dup pairs
    u64* xsu = (u64*)xsf;
    const int tid = threadIdx.x;
    for (int idx = tid; idx < G3 * DD; idx += 384) {
        const int j = idx >> 7, k = idx & 127;
        sm[k * S_GRU + j] = Whh[idx];
    }
    for (int idx = tid; idx < 2048; idx += 384) xsf[idx] = 0.0f;
    __syncthreads();

    const int lane = tid & 31, wid = tid >> 5;
    const int gr = wid / 6, rem = wid - gr * 6;
    const int g = rem >> 1, ks = rem & 1;
    const int row0 = blockIdx.x * 8 + gr * 4;

    u64 bv0 = pack2(0.f, 0.f), bv1 = bv0;
    if (ks == 0) {
        bv0 = pack2(bhh[g * 128 + 4 * lane], bhh[g * 128 + 4 * lane + 1]);
        bv1 = pack2(bhh[g * 128 + 4 * lane + 2], bhh[g * 128 + 4 * lane + 3]);
    }
    const float* wb = sm + g * 128 + 4 * lane;
    float* pme = pbuf + (size_t)((gr * 3 + g) * 4) * 128 + 4 * lane;

    float h[4][4];      // live only in (g==2, ks==0) warps
#pragma unroll
    for (int r = 0; r < 4; r++)
#pragma unroll
        for (int m = 0; m < 4; m++) h[r][m] = 0.0f;

    for (int t = 0; t < TT; t++) {
        float4 gvec[4];
        if (ks == 0) {
#pragma unroll
            for (int r = 0; r < 4; r++)
                gvec[r] = *(const float4*)(gi + ((size_t)t * BATCH + row0 + r) * G3 +
                                           g * 128 + 4 * lane);
        }
        u64 acc[4][2];
#pragma unroll
        for (int r = 0; r < 4; r++) { acc[r][0] = bv0; acc[r][1] = bv1; }

        const int kbase = 64 * ks;
#pragma unroll 4
        for (int kk = 0; kk < 64; kk += 2) {
            const int k = kbase + kk;
            const ulonglong2 x0 = *(const ulonglong2*)(xsu + (gr * 4 + 0) * 128 + k);
            const ulonglong2 x1 = *(const ulonglong2*)(xsu + (gr * 4 + 1) * 128 + k);
            const ulonglong2 x2 = *(const ulonglong2*)(xsu + (gr * 4 + 2) * 128 + k);
            const ulonglong2 x3 = *(const ulonglong2*)(xsu + (gr * 4 + 3) * 128 + k);
            const ulonglong2 wA = *(const ulonglong2*)(wb + k * S_GRU);
            const ulonglong2 wB = *(const ulonglong2*)(wb + (k + 1) * S_GRU);
            acc[0][0] = ffma2(x0.x, wA.x, acc[0][0]); acc[0][1] = ffma2(x0.x, wA.y, acc[0][1]);
            acc[1][0] = ffma2(x1.x, wA.x, acc[1][0]); acc[1][1] = ffma2(x1.x, wA.y, acc[1][1]);
            acc[2][0] = ffma2(x2.x, wA.x, acc[2][0]); acc[2][1] = ffma2(x2.x, wA.y, acc[2][1]);
            acc[3][0] = ffma2(x3.x, wA.x, acc[3][0]); acc[3][1] = ffma2(x3.x, wA.y, acc[3][1]);
            acc[0][0] = ffma2(x0.y, wB.x, acc[0][0]); acc[0][1] = ffma2(x0.y, wB.y, acc[0][1]);
            acc[1][0] = ffma2(x1.y, wB.x, acc[1][0]); acc[1][1] = ffma2(x1.y, wB.y, acc[1][1]);
            acc[2][0] = ffma2(x2.y, wB.x, acc[2][0]); acc[2][1] = ffma2(x2.y, wB.y, acc[2][1]);
            acc[3][0] = ffma2(x3.y, wB.x, acc[3][0]); acc[3][1] = ffma2(x3.y, wB.y, acc[3][1]);
        }
        if (ks == 1) {
#pragma unroll
            for (int r = 0; r < 4; r++)
                *(ulonglong2*)(pme + r * 128) = make_ulonglong2(acc[r][0], acc[r][1]);
        }
        __syncthreads();   // A: ks1 raw partials visible

        float np[4][4];
        if (ks == 0) {
#pragma unroll
            for (int r = 0; r < 4; r++) {
                const ulonglong2 p = *(const ulonglong2*)(pme + r * 128);
                const u64 s0 = fadd2(acc[r][0], p.x), s1 = fadd2(acc[r][1], p.y);
                float a0, a1, a2, a3;
                unpk2(s0, a0, a1); unpk2(s1, a2, a3);
                if (g < 2) {
                    // r/z gate: sigmoid, overwrite pbuf slot with gate values
                    *(float4*)(pme + r * 128) =
                        make_float4(fsigm(gvec[r].x + a0), fsigm(gvec[r].y + a1),
                                    fsigm(gvec[r].z + a2), fsigm(gvec[r].w + a3));
                } else {
                    np[r][0] = a0; np[r][1] = a1; np[r][2] = a2; np[r][3] = a3;
                }
            }
        }
        __syncthreads();   // B: r/z gate values visible

        if (ks == 0 && g == 2) {
            float* rb = pbuf + (size_t)(gr * 3 + 0) * 4 * 128 + 4 * lane;
            float* zb = pbuf + (size_t)(gr * 3 + 1) * 4 * 128 + 4 * lane;
#pragma unroll
            for (int r = 0; r < 4; r++) {
                const float4 rv = *(const float4*)(rb + r * 128);
                const float4 zv = *(const float4*)(zb + r * 128);
                const float n0 = ftanh(gvec[r].x + rv.x * np[r][0]);
                const float n1 = ftanh(gvec[r].y + rv.y * np[r][1]);
                const float n2 = ftanh(gvec[r].z + rv.z * np[r][2]);
                const float n3 = ftanh(gvec[r].w + rv.w * np[r][3]);
                h[r][0] = n0 + zv.x * (h[r][0] - n0);
                h[r][1] = n1 + zv.y * (h[r][1] - n1);
                h[r][2] = n2 + zv.z * (h[r][2] - n2);
                h[r][3] = n3 + zv.w * (h[r][3] - n3);
                float* xme = xsf + (size_t)((gr * 4 + r) * 128 + 4 * lane) * 2;
                *(float4*)(xme)     = make_float4(h[r][0], h[r][0], h[r][1], h[r][1]);
                *(float4*)(xme + 4) = make_float4(h[r][2], h[r][2], h[r][3], h[r][3]);
                if (otraj)
                    *(float4*)(otraj + ((size_t)t * BATCH + row0 + r) * DD + 4 * lane) =
                        make_float4(h[r][0], h[r][1], h[r][2], h[r][3]);
            }
        }
        __syncthreads();   // C: new h visible for next matvec
    }
    if (olast && ks == 0 && g == 2) {
#pragma unroll
        for (int r = 0; r < 4; r++)
            *(float4*)(olast + (size_t)(row0 + r) * DD + 4 * lane) =
                make_float4(h[r][0], h[r][1], h[r][2], h[r][3]);
    }
}

// ---------------------------------------------------------------------------
// Phase 6: FC head (unchanged).
// ---------------------------------------------------------------------------
__global__ void __launch_bounds__(256)
fc_kernel(const float* __restrict__ W1, const float* __restrict__ b1,
          const float* __restrict__ W2, const float* __restrict__ b2,
          float* __restrict__ out)
{
    extern __shared__ float sm[];
    float* hs = sm;
    float* hd = sm + 1024;
    float* wt = sm + 1536;
    const int tid = threadIdx.x;
    const int row0 = blockIdx.x * 8;

    for (int idx = tid; idx < 8 * DD; idx += 256) hs[idx] = g_h2[(size_t)row0 * DD + idx];
    for (int idx = tid; idx < 64 * DD; idx += 256) {
        const int j = idx >> 7, k = idx & 127;
        wt[k * 68 + j] = W1[idx];
    }
    __syncthreads();

#pragma unroll
    for (int i = 0; i < 2; i++) {
        const int p = tid + 256 * i, r = p >> 6, j = p & 63;
        float acc = b1[j];
#pragma unroll 8
        for (int k = 0; k < DD; k++) acc = fmaf(hs[r * DD + k], wt[k * 68 + j], acc);
        hd[r * 64 + j] = acc * normcdff(acc);
    }

    for (int c = 0; c < 12; c++) {
        __syncthreads();
        for (int idx = tid; idx < 256 * 64; idx += 256) {
            const int jj = idx >> 6, k = idx & 63;
            wt[k * 260 + jj] = W2[(size_t)(c * 256 + jj) * 64 + k];
        }
        __syncthreads();
        const int j = c * 256 + tid;
        float acc[8];
#pragma unroll
        for (int r = 0; r < 8; r++) acc[r] = b2[j];
#pragma unroll 8
        for (int k = 0; k < 64; k++) {
            const float w = wt[k * 260 + tid];
#pragma unroll
            for (int r = 0; r < 8; r++) acc[r] = fmaf(hd[r * 64 + k], w, acc[r]);
        }
#pragma unroll
        for (int r = 0; r < 8; r++) out[(size_t)(row0 + r) * 3072 + j] = acc[r];
    }
}

// ---------------------------------------------------------------------------
extern "C" void kernel_launch(void* const* d_in, const int* in_sizes, int n_in,
                              void* d_out, int out_size)
{
    (void)in_sizes; (void)n_in; (void)out_size;
    const float* yl    = (const float*)d_in[1];
    const float* yh    = (const float*)d_in[2];
    const float* W_ode = (const float*)d_in[3];
    const float* b_ode = (const float*)d_in[4];
    const float* W_ih0 = (const float*)d_in[5];
    const float* W_hh0 = (const float*)d_in[6];
    const float* b_ih0 = (const float*)d_in[7];
    const float* b_hh0 = (const float*)d_in[8];
    const float* W_ih1 = (const float*)d_in[9];
    const float* W_hh1 = (const float*)d_in[10];
    const float* b_ih1 = (const float*)d_in[11];
    const float* b_hh1 = (const float*)d_in[12];
    const float* W1    = (const float*)d_in[13];
    const float* b1    = (const float*)d_in[14];
    const float* W2    = (const float*)d_in[15];
    const float* b2    = (const float*)d_in[16];
    float* out = (float*)d_out;

    float *traj, *gibuf, *h1, *h2;
    cudaGetSymbolAddress((void**)&traj,  g_traj);
    cudaGetSymbolAddress((void**)&gibuf, g_gi);
    cudaGetSymbolAddress((void**)&h1,    g_h1);
    cudaGetSymbolAddress((void**)&h2,    g_h2);

    const int SM_ODE = (S_ODE * DD + 4096 + 2048) * 4;   //  92,160 B
    const int SM_GI  = S_GRU * DD * 4;                   // 198,656 B
    const int SM_GRU2 = (S_GRU * DD + 3072 + 2048) * 4;  // 219,136 B
    const int SM_FC  = (1536 + 64 * 260) * 4;            //  72,704 B
    cudaFuncSetAttribute(ode_kernel, cudaFuncAttributeMaxDynamicSharedMemorySize, SM_ODE);
    cudaFuncSetAttribute(gi_kernel,  cudaFuncAttributeMaxDynamicSharedMemorySize, SM_GI);
    cudaFuncSetAttribute(gru_kernel, cudaFuncAttributeMaxDynamicSharedMemorySize, SM_GRU2);
    cudaFuncSetAttribute(fc_kernel,  cudaFuncAttributeMaxDynamicSharedMemorySize, SM_FC);

    ode_kernel<<<128, 256, SM_ODE>>>(yl, yh, W_ode, b_ode);
    gi_kernel <<<128, 512, SM_GI>>>(traj, W_ih0, b_ih0, gibuf);
    gru_kernel<<<128, 384, SM_GRU2>>>(gibuf, W_hh0, b_hh0, h1, nullptr);
    gi_kernel <<<128, 512, SM_GI>>>(h1, W_ih1, b_ih1, gibuf);
    gru_kernel<<<128, 384, SM_GRU2>>>(gibuf, W_hh1, b_hh1, nullptr, h2);
    fc_kernel <<<128, 256, SM_FC>>>(W1, b1, W2, b2, out);
}